// round 11
// baseline (speedup 1.0000x reference)
#include <cuda_runtime.h>
#include <cuda_bf16.h>
#include <math_constants.h>

// ---------------------------------------------------------------------------
// MHA_962072674722 (b=2, s=2048, dim=1024, 16 heads x 64)
// R11: register-local PV (P C-frag == bf16 A-frag identity), split-bf16 V,
//      cp.async double-buffered attention staging. GEMMs as R10.
// ---------------------------------------------------------------------------

// ---- pre-split operand buffers -------------------------------------------
__device__ __nv_bfloat16 g_qh[4096 * 1024],  g_ql[4096 * 1024];
__device__ __nv_bfloat16 g_WqhT[1024 * 1024], g_WqlT[1024 * 1024];
__device__ __nv_bfloat16 g_WkhT[1024 * 1024], g_WklT[1024 * 1024];
__device__ __nv_bfloat16 g_WvhT[1024 * 1024], g_WvlT[1024 * 1024];
__device__ __nv_bfloat16 g_WohT[1024 * 1024], g_WolT[1024 * 1024];
__device__ __nv_bfloat16 g_Qh[4096 * 1024],  g_Ql[4096 * 1024];    // scaled Q split
__device__ __nv_bfloat16 g_Kh[4096 * 1024],  g_Kl[4096 * 1024];    // K split
__device__ __nv_bfloat16 g_Vh[4096 * 1024],  g_Vl[4096 * 1024];    // V split [b,h,d,j]
__device__ __nv_bfloat16 g_ATTh[4096 * 1024], g_ATTl[4096 * 1024];

// ---- helpers --------------------------------------------------------------
__device__ __forceinline__ void split_bf(float x, __nv_bfloat16& h, __nv_bfloat16& l) {
    h = __float2bfloat16(x);
    l = __float2bfloat16(x - __bfloat162float(h));
}
__device__ __forceinline__ unsigned pack2(__nv_bfloat16 a, __nv_bfloat16 b) {
    __nv_bfloat162 p = {a, b};
    return *reinterpret_cast<unsigned*>(&p);
}
__device__ __forceinline__ void mma_bf16(float c[4], const unsigned a[4],
                                         unsigned b0, unsigned b1) {
    asm("mma.sync.aligned.m16n8k16.row.col.f32.bf16.bf16.f32 "
        "{%0,%1,%2,%3},{%4,%5,%6,%7},{%8,%9},{%0,%1,%2,%3};"
        : "+f"(c[0]), "+f"(c[1]), "+f"(c[2]), "+f"(c[3])
        : "r"(a[0]), "r"(a[1]), "r"(a[2]), "r"(a[3]), "r"(b0), "r"(b1));
}
__device__ __forceinline__ void cp16(void* dst, const void* src) {
    unsigned d = (unsigned)__cvta_generic_to_shared(dst);
    asm volatile("cp.async.cg.shared.global [%0], [%1], 16;"
                 :: "r"(d), "l"(src) : "memory");
}

// ---------------------------------------------------------------------------
// Prep: elementwise fp32 -> (hi, lo) bf16 split. n4 = elems/4.
// ---------------------------------------------------------------------------
__global__ __launch_bounds__(256) void split_mat(
    const float* __restrict__ in, __nv_bfloat16* __restrict__ h,
    __nv_bfloat16* __restrict__ l, int n4)
{
    int i = blockIdx.x * blockDim.x + threadIdx.x;
    if (i >= n4) return;
    float4 v = reinterpret_cast<const float4*>(in)[i];
    __nv_bfloat16 h0, l0, h1, l1, h2, l2, h3, l3;
    split_bf(v.x, h0, l0); split_bf(v.y, h1, l1);
    split_bf(v.z, h2, l2); split_bf(v.w, h3, l3);
    reinterpret_cast<uint2*>(h)[i] = make_uint2(pack2(h0, h1), pack2(h2, h3));
    reinterpret_cast<uint2*>(l)[i] = make_uint2(pack2(l0, l1), pack2(l2, l3));
}

// ---------------------------------------------------------------------------
// Prep: split + transpose weight block -> [n][k] bf16 hi/lo.
// ---------------------------------------------------------------------------
__global__ __launch_bounds__(256) void split_transpose(
    const float* __restrict__ W, int ldw, int col0,
    __nv_bfloat16* __restrict__ hT, __nv_bfloat16* __restrict__ lT)
{
    __shared__ float t[32][33];
    const int tx = threadIdx.x, ty = threadIdx.y;
    const int co = blockIdx.x * 32, k0 = blockIdx.y * 32;
#pragma unroll
    for (int i = ty; i < 32; i += 8)
        t[i][tx] = W[(size_t)(k0 + i) * ldw + col0 + co + tx];
    __syncthreads();
#pragma unroll
    for (int i = ty; i < 32; i += 8) {
        float v = t[tx][i];
        __nv_bfloat16 h, l;
        split_bf(v, h, l);
        hT[(size_t)(co + i) * 1024 + k0 + tx] = h;
        lT[(size_t)(co + i) * 1024 + k0 + tx] = l;
    }
}

// ---------------------------------------------------------------------------
// Pipelined 3xBF16 GEMM on pre-split operands (as R10).
// MODE 0: fp32 out. MODE 1: split bf16 out ((acc+bias)*scale).
// MODE 2: split bf16 out, transposed to [b,h,d,j] (attention V operand).
// ---------------------------------------------------------------------------
#define ARR   (128 * 40)
#define STAGE (4 * ARR)

template <int MODE>
__global__ __launch_bounds__(256, 2) void gemm_ps(
    const __nv_bfloat16* __restrict__ Ah, const __nv_bfloat16* __restrict__ Al,
    const __nv_bfloat16* __restrict__ BhT, const __nv_bfloat16* __restrict__ BlT,
    const float* __restrict__ bias, float scale,
    float* __restrict__ outF,
    __nv_bfloat16* __restrict__ outH, __nv_bfloat16* __restrict__ outL)
{
    extern __shared__ __nv_bfloat16 sm[];
    const int tid = threadIdx.x, lane = tid & 31, w = tid >> 5;
    const int m0 = blockIdx.y * 128, n0 = blockIdx.x * 128;
    const int wm = (w & 3) * 32, wn = (w >> 2) * 64;
    const int r = lane >> 2, cq = lane & 3;

    float acc[2][8][4];
#pragma unroll
    for (int mt = 0; mt < 2; mt++)
#pragma unroll
        for (int nt = 0; nt < 8; nt++)
#pragma unroll
            for (int i = 0; i < 4; i++) acc[mt][nt][i] = 0.f;

    const int srow = tid >> 1, scb = (tid & 1) * 16;
    const __nv_bfloat16* gAh = Ah + (size_t)(m0 + srow) * 1024 + scb;
    const __nv_bfloat16* gAl = Al + (size_t)(m0 + srow) * 1024 + scb;
    const __nv_bfloat16* gBh = BhT + (size_t)(n0 + srow) * 1024 + scb;
    const __nv_bfloat16* gBl = BlT + (size_t)(n0 + srow) * 1024 + scb;
    const int so = srow * 40 + scb;

    auto stage = [&](int kt, int buf) {
        __nv_bfloat16* s = sm + buf * STAGE;
        const int go = kt * 32;
        cp16(s + so,           gAh + go); cp16(s + so + 8,           gAh + go + 8);
        cp16(s + ARR + so,     gAl + go); cp16(s + ARR + so + 8,     gAl + go + 8);
        cp16(s + 2 * ARR + so, gBh + go); cp16(s + 2 * ARR + so + 8, gBh + go + 8);
        cp16(s + 3 * ARR + so, gBl + go); cp16(s + 3 * ARR + so + 8, gBl + go + 8);
        asm volatile("cp.async.commit_group;" ::: "memory");
    };

    stage(0, 0);
    stage(1, 1);

    for (int kt = 0; kt < 32; kt++) {
        if (kt + 1 < 32) asm volatile("cp.async.wait_group 1;" ::: "memory");
        else             asm volatile("cp.async.wait_group 0;" ::: "memory");
        __syncthreads();

        const __nv_bfloat16* s = sm + (kt & 1) * STAGE;
#pragma unroll
        for (int ks = 0; ks < 2; ks++) {
            const int kk = ks * 16;
            unsigned ah[2][4], al4[2][4];
#pragma unroll
            for (int mt = 0; mt < 2; mt++) {
                const int mr = wm + mt * 16;
                ah[mt][0]  = *(const unsigned*)&s[(mr + r) * 40 + kk + cq * 2];
                ah[mt][1]  = *(const unsigned*)&s[(mr + r + 8) * 40 + kk + cq * 2];
                ah[mt][2]  = *(const unsigned*)&s[(mr + r) * 40 + kk + cq * 2 + 8];
                ah[mt][3]  = *(const unsigned*)&s[(mr + r + 8) * 40 + kk + cq * 2 + 8];
                al4[mt][0] = *(const unsigned*)&s[ARR + (mr + r) * 40 + kk + cq * 2];
                al4[mt][1] = *(const unsigned*)&s[ARR + (mr + r + 8) * 40 + kk + cq * 2];
                al4[mt][2] = *(const unsigned*)&s[ARR + (mr + r) * 40 + kk + cq * 2 + 8];
                al4[mt][3] = *(const unsigned*)&s[ARR + (mr + r + 8) * 40 + kk + cq * 2 + 8];
            }
#pragma unroll
            for (int nt = 0; nt < 8; nt++) {
                const int base = (wn + nt * 8 + r) * 40 + kk + cq * 2;
                const unsigned bh0 = *(const unsigned*)&s[2 * ARR + base];
                const unsigned bh1 = *(const unsigned*)&s[2 * ARR + base + 8];
                const unsigned bl0 = *(const unsigned*)&s[3 * ARR + base];
                const unsigned bl1 = *(const unsigned*)&s[3 * ARR + base + 8];
#pragma unroll
                for (int mt = 0; mt < 2; mt++) {
                    mma_bf16(acc[mt][nt], ah[mt],  bh0, bh1);
                    mma_bf16(acc[mt][nt], ah[mt],  bl0, bl1);
                    mma_bf16(acc[mt][nt], al4[mt], bh0, bh1);
                }
            }
        }
        __syncthreads();
        if (kt + 2 < 32) stage(kt + 2, kt & 1);
    }

    // ---- epilogue -------------------------------------------------------
#pragma unroll
    for (int nt = 0; nt < 8; nt++) {
        const int col = n0 + wn + nt * 8 + cq * 2;
        const float b0 = __ldg(bias + col), b1 = __ldg(bias + col + 1);
#pragma unroll
        for (int mt = 0; mt < 2; mt++) {
            const int row = m0 + wm + mt * 16 + r;
            float v00 = acc[mt][nt][0] + b0, v01 = acc[mt][nt][1] + b1;
            float v10 = acc[mt][nt][2] + b0, v11 = acc[mt][nt][3] + b1;
            if (MODE == 0) {
                *reinterpret_cast<float2*>(outF + (size_t)row * 1024 + col) =
                    make_float2(v00, v01);
                *reinterpret_cast<float2*>(outF + (size_t)(row + 8) * 1024 + col) =
                    make_float2(v10, v11);
            } else if (MODE == 1) {
                v00 *= scale; v01 *= scale; v10 *= scale; v11 *= scale;
                __nv_bfloat16 h0, l0, h1, l1;
                split_bf(v00, h0, l0); split_bf(v01, h1, l1);
                *(unsigned*)&outH[(size_t)row * 1024 + col] = pack2(h0, h1);
                *(unsigned*)&outL[(size_t)row * 1024 + col] = pack2(l0, l1);
                split_bf(v10, h0, l0); split_bf(v11, h1, l1);
                *(unsigned*)&outH[(size_t)(row + 8) * 1024 + col] = pack2(h0, h1);
                *(unsigned*)&outL[(size_t)(row + 8) * 1024 + col] = pack2(l0, l1);
            } else {
                // V split, transposed: [((b*16+h)*64+d)*2048 + j]
                const size_t base = (size_t)((row >> 11) * 16 + (col >> 6)) * 64;
                const int d = col & 63;
                const int j0 = row & 2047, j1 = j0 + 8;
                __nv_bfloat16 h, l;
                split_bf(v00, h, l);
                outH[(base + d) * 2048 + j0] = h;  outL[(base + d) * 2048 + j0] = l;
                split_bf(v01, h, l);
                outH[(base + d + 1) * 2048 + j0] = h;  outL[(base + d + 1) * 2048 + j0] = l;
                split_bf(v10, h, l);
                outH[(base + d) * 2048 + j1] = h;  outL[(base + d) * 2048 + j1] = l;
                split_bf(v11, h, l);
                outH[(base + d + 1) * 2048 + j1] = h;  outL[(base + d + 1) * 2048 + j1] = l;
            }
        }
    }
}

// ---------------------------------------------------------------------------
// Flash attention, fully register-resident P, cp.async double-buffered K/V.
// Block = 128 q-rows x head x batch, 8 warps. S: 3xBF16. PV: 3xBF16 with
// P packed straight from S-fragments (C-frag == A-frag layout identity).
// smem: 2 stages x (Kh|Kl|Vh|Vl)[64][72] bf16 = 73728 B.
// ---------------------------------------------------------------------------
#define AT_ARR (64 * 72)
#define AT_STG (4 * AT_ARR)

__global__ __launch_bounds__(256) void attn_mma(
    const __nv_bfloat16* __restrict__ Qh, const __nv_bfloat16* __restrict__ Ql,
    const __nv_bfloat16* __restrict__ Kh, const __nv_bfloat16* __restrict__ Kl,
    const __nv_bfloat16* __restrict__ Vh, const __nv_bfloat16* __restrict__ Vl,
    __nv_bfloat16* __restrict__ ATTh, __nv_bfloat16* __restrict__ ATTl)
{
    extern __shared__ __nv_bfloat16 smb[];

    const int tid = threadIdx.x, lane = tid & 31, w = tid >> 5;
    const int b = blockIdx.z, h = blockIdx.y, qt = blockIdx.x;
    const int r = lane >> 2, cq = lane & 3;
    const int wrow = w * 16;
    const int qrow0 = b * 2048 + qt * 128;

    // --- Q fragments: direct from pre-split global (once) ---
    unsigned qh[4][4], ql4[4][4];
#pragma unroll
    for (int ks = 0; ks < 4; ks++)
#pragma unroll
        for (int fi = 0; fi < 4; fi++) {
            const int rr = qrow0 + wrow + r + (fi & 1) * 8;
            const int cc = h * 64 + ks * 16 + cq * 2 + (fi >> 1) * 8;
            qh[ks][fi]  = *(const unsigned*)&Qh[(size_t)rr * 1024 + cc];
            ql4[ks][fi] = *(const unsigned*)&Ql[(size_t)rr * 1024 + cc];
        }

    float o[8][4];
#pragma unroll
    for (int nt = 0; nt < 8; nt++)
#pragma unroll
        for (int i = 0; i < 4; i++) o[nt][i] = 0.f;
    float mr0 = -CUDART_INF_F, mr1 = -CUDART_INF_F;
    float lr0 = 0.f, lr1 = 0.f;

    // staging maps: row = tid>>2 (0..63), 16-elem chunk = (tid&3)*16
    const int srow = tid >> 2, scb = (tid & 3) * 16;
    const size_t kgbase = (size_t)(b * 2048 + srow) * 1024 + h * 64 + scb;
    const size_t vgbase = (size_t)((b * 16 + h) * 64 + srow) * 2048 + scb;
    const int so = srow * 72 + scb;

    auto stage = [&](int kt, int buf) {
        __nv_bfloat16* s = smb + buf * AT_STG;
        const size_t kg = kgbase + (size_t)kt * 64 * 1024;
        const size_t vg = vgbase + kt * 64;
        cp16(s + so,              Kh + kg); cp16(s + so + 8,              Kh + kg + 8);
        cp16(s + AT_ARR + so,     Kl + kg); cp16(s + AT_ARR + so + 8,     Kl + kg + 8);
        cp16(s + 2 * AT_ARR + so, Vh + vg); cp16(s + 2 * AT_ARR + so + 8, Vh + vg + 8);
        cp16(s + 3 * AT_ARR + so, Vl + vg); cp16(s + 3 * AT_ARR + so + 8, Vl + vg + 8);
        asm volatile("cp.async.commit_group;" ::: "memory");
    };

    stage(0, 0);

    for (int kt = 0; kt < 32; kt++) {
        if (kt + 1 < 32) {
            stage(kt + 1, (kt + 1) & 1);
            asm volatile("cp.async.wait_group 1;" ::: "memory");
        } else {
            asm volatile("cp.async.wait_group 0;" ::: "memory");
        }
        __syncthreads();

        const __nv_bfloat16* Khs = smb + (kt & 1) * AT_STG;
        const __nv_bfloat16* Kls = Khs + AT_ARR;
        const __nv_bfloat16* Vhs = Khs + 2 * AT_ARR;
        const __nv_bfloat16* Vls = Khs + 3 * AT_ARR;

        // ---- S = Q @ K^T (3xBF16, k16) ----
        float s[8][4];
#pragma unroll
        for (int nt = 0; nt < 8; nt++)
#pragma unroll
            for (int i = 0; i < 4; i++) s[nt][i] = 0.f;

#pragma unroll
        for (int ks = 0; ks < 4; ks++) {
            const int kk = ks * 16;
#pragma unroll
            for (int nt = 0; nt < 8; nt++) {
                const int base = (nt * 8 + r) * 72 + kk + cq * 2;
                const unsigned bh0 = *(const unsigned*)&Khs[base];
                const unsigned bh1 = *(const unsigned*)&Khs[base + 8];
                const unsigned bl0 = *(const unsigned*)&Kls[base];
                const unsigned bl1 = *(const unsigned*)&Kls[base + 8];
                mma_bf16(s[nt], qh[ks],  bh0, bh1);
                mma_bf16(s[nt], qh[ks],  bl0, bl1);
                mma_bf16(s[nt], ql4[ks], bh0, bh1);
            }
        }

        // ---- online softmax (all in registers) ----
        float tm0 = -CUDART_INF_F, tm1 = -CUDART_INF_F;
#pragma unroll
        for (int nt = 0; nt < 8; nt++) {
            tm0 = fmaxf(tm0, fmaxf(s[nt][0], s[nt][1]));
            tm1 = fmaxf(tm1, fmaxf(s[nt][2], s[nt][3]));
        }
        tm0 = fmaxf(tm0, __shfl_xor_sync(0xffffffffu, tm0, 1));
        tm0 = fmaxf(tm0, __shfl_xor_sync(0xffffffffu, tm0, 2));
        tm1 = fmaxf(tm1, __shfl_xor_sync(0xffffffffu, tm1, 1));
        tm1 = fmaxf(tm1, __shfl_xor_sync(0xffffffffu, tm1, 2));

        const float mn0 = fmaxf(mr0, tm0), mn1 = fmaxf(mr1, tm1);
        const float c0 = __expf(mr0 - mn0), c1 = __expf(mr1 - mn1);
        float ps0 = 0.f, ps1 = 0.f;
#pragma unroll
        for (int nt = 0; nt < 8; nt++) {
            s[nt][0] = __expf(s[nt][0] - mn0);
            s[nt][1] = __expf(s[nt][1] - mn0);
            s[nt][2] = __expf(s[nt][2] - mn1);
            s[nt][3] = __expf(s[nt][3] - mn1);
            ps0 += s[nt][0] + s[nt][1]; ps1 += s[nt][2] + s[nt][3];
            o[nt][0] *= c0; o[nt][1] *= c0; o[nt][2] *= c1; o[nt][3] *= c1;
        }
        ps0 += __shfl_xor_sync(0xffffffffu, ps0, 1);
        ps0 += __shfl_xor_sync(0xffffffffu, ps0, 2);
        ps1 += __shfl_xor_sync(0xffffffffu, ps1, 1);
        ps1 += __shfl_xor_sync(0xffffffffu, ps1, 2);
        lr0 = lr0 * c0 + ps0; lr1 = lr1 * c1 + ps1;
        mr0 = mn0; mr1 = mn1;

        // ---- pack P straight into bf16 A-fragments (hi/lo) ----
        unsigned ph[4][4], pl[4][4];
#pragma unroll
        for (int ks = 0; ks < 4; ks++) {
            const int e = 2 * ks, oo = 2 * ks + 1;
            __nv_bfloat16 h0, l0, h1, l1;
            split_bf(s[e][0], h0, l0);  split_bf(s[e][1], h1, l1);
            ph[ks][0] = pack2(h0, h1);  pl[ks][0] = pack2(l0, l1);
            split_bf(s[e][2], h0, l0);  split_bf(s[e][3], h1, l1);
            ph[ks][1] = pack2(h0, h1);  pl[ks][1] = pack2(l0, l1);
            split_bf(s[oo][0], h0, l0); split_bf(s[oo][1], h1, l1);
            ph[ks][2] = pack2(h0, h1);  pl[ks][2] = pack2(l0, l1);
            split_bf(s[oo][2], h0, l0); split_bf(s[oo][3], h1, l1);
            ph[ks][3] = pack2(h0, h1);  pl[ks][3] = pack2(l0, l1);
        }

        // ---- O += P @ V (3xBF16, register-local P) ----
#pragma unroll
        for (int ks = 0; ks < 4; ks++) {
            const int kk = ks * 16;
#pragma unroll
            for (int nt = 0; nt < 8; nt++) {
                const int base = (nt * 8 + r) * 72 + kk + cq * 2;
                const unsigned vh0 = *(const unsigned*)&Vhs[base];
                const unsigned vh1 = *(const unsigned*)&Vhs[base + 8];
                const unsigned vl0 = *(const unsigned*)&Vls[base];
                const unsigned vl1 = *(const unsigned*)&Vls[base + 8];
                mma_bf16(o[nt], ph[ks], vh0, vh1);
                mma_bf16(o[nt], ph[ks], vl0, vl1);
                mma_bf16(o[nt], pl[ks], vh0, vh1);
            }
        }
        __syncthreads();   // readers done before buffer (kt+2)&1 == kt&1 reuse
    }

    // ---- epilogue: split store to ATTh/ATTl ----
    const float i0 = 1.f / lr0, i1 = 1.f / lr1;
#pragma unroll
    for (int nt = 0; nt < 8; nt++) {
        const int col = h * 64 + nt * 8 + cq * 2;
        const int row = qrow0 + wrow + r;
        __nv_bfloat16 h0, l0, h1, l1;
        split_bf(o[nt][0] * i0, h0, l0); split_bf(o[nt][1] * i0, h1, l1);
        *(unsigned*)&ATTh[(size_t)row * 1024 + col] = pack2(h0, h1);
        *(unsigned*)&ATTl[(size_t)row * 1024 + col] = pack2(l0, l1);
        split_bf(o[nt][2] * i1, h0, l0); split_bf(o[nt][3] * i1, h1, l1);
        *(unsigned*)&ATTh[(size_t)(row + 8) * 1024 + col] = pack2(h0, h1);
        *(unsigned*)&ATTl[(size_t)(row + 8) * 1024 + col] = pack2(l0, l1);
    }
}

// ---------------------------------------------------------------------------
extern "C" void kernel_launch(void* const* d_in, const int* in_sizes, int n_in,
                              void* d_out, int out_size)
{
    const float* q   = (const float*)d_in[0];
    const float* Wq  = (const float*)d_in[1];
    const float* bq  = (const float*)d_in[2];
    const float* Wkv = (const float*)d_in[3];
    const float* bkv = (const float*)d_in[4];
    const float* Wo  = (const float*)d_in[5];
    const float* bo  = (const float*)d_in[6];
    float* out = (float*)d_out;

    __nv_bfloat16 *qh, *ql, *WqhT, *WqlT, *WkhT, *WklT, *WvhT, *WvlT, *WohT, *WolT;
    __nv_bfloat16 *Qh, *Ql, *Kh, *Kl, *Vh, *Vl, *ATTh, *ATTl;
    cudaGetSymbolAddress((void**)&qh, g_qh);     cudaGetSymbolAddress((void**)&ql, g_ql);
    cudaGetSymbolAddress((void**)&WqhT, g_WqhT); cudaGetSymbolAddress((void**)&WqlT, g_WqlT);
    cudaGetSymbolAddress((void**)&WkhT, g_WkhT); cudaGetSymbolAddress((void**)&WklT, g_WklT);
    cudaGetSymbolAddress((void**)&WvhT, g_WvhT); cudaGetSymbolAddress((void**)&WvlT, g_WvlT);
    cudaGetSymbolAddress((void**)&WohT, g_WohT); cudaGetSymbolAddress((void**)&WolT, g_WolT);
    cudaGetSymbolAddress((void**)&Qh, g_Qh);     cudaGetSymbolAddress((void**)&Ql, g_Ql);
    cudaGetSymbolAddress((void**)&Kh, g_Kh);     cudaGetSymbolAddress((void**)&Kl, g_Kl);
    cudaGetSymbolAddress((void**)&Vh, g_Vh);     cudaGetSymbolAddress((void**)&Vl, g_Vl);
    cudaGetSymbolAddress((void**)&ATTh, g_ATTh); cudaGetSymbolAddress((void**)&ATTl, g_ATTl);

    const int GEMM_SMEM = 2 * STAGE * 2;        // 81920 B
    const int ATTN_SMEM = 2 * AT_STG * 2;       // 73728 B
    cudaFuncSetAttribute(gemm_ps<0>, cudaFuncAttributeMaxDynamicSharedMemorySize, GEMM_SMEM);
    cudaFuncSetAttribute(gemm_ps<1>, cudaFuncAttributeMaxDynamicSharedMemorySize, GEMM_SMEM);
    cudaFuncSetAttribute(gemm_ps<2>, cudaFuncAttributeMaxDynamicSharedMemorySize, GEMM_SMEM);
    cudaFuncSetAttribute(attn_mma, cudaFuncAttributeMaxDynamicSharedMemorySize, ATTN_SMEM);

    // --- prep ---
    split_mat<<<4096, 256>>>(q, qh, ql, 4096 * 1024 / 4);
    split_transpose<<<dim3(32, 32), dim3(32, 8)>>>(Wq, 1024, 0, WqhT, WqlT);
    split_transpose<<<dim3(32, 32), dim3(32, 8)>>>(Wkv, 2048, 0, WkhT, WklT);
    split_transpose<<<dim3(32, 32), dim3(32, 8)>>>(Wkv, 2048, 1024, WvhT, WvlT);
    split_transpose<<<dim3(32, 32), dim3(32, 8)>>>(Wo, 1024, 0, WohT, WolT);

    // --- projections ---
    gemm_ps<1><<<dim3(8, 32), 256, GEMM_SMEM>>>(qh, ql, WqhT, WqlT, bq, 0.125f,
                                                nullptr, Qh, Ql);
    gemm_ps<1><<<dim3(8, 32), 256, GEMM_SMEM>>>(qh, ql, WkhT, WklT, bkv, 1.0f,
                                                nullptr, Kh, Kl);
    gemm_ps<2><<<dim3(8, 32), 256, GEMM_SMEM>>>(qh, ql, WvhT, WvlT, bkv + 1024, 1.0f,
                                                nullptr, Vh, Vl);
    // --- attention ---
    attn_mma<<<dim3(16, 16, 2), 256, ATTN_SMEM>>>(Qh, Ql, Kh, Kl, Vh, Vl, ATTh, ATTl);
    // --- output projection ---
    gemm_ps<0><<<dim3(8, 32), 256, GEMM_SMEM>>>(ATTh, ATTl, WohT, WolT, bo, 1.0f,
                                                out, nullptr, nullptr);
}

// round 14
// speedup vs baseline: 1.0391x; 1.0391x over previous
#include <cuda_runtime.h>
#include <cuda_bf16.h>
#include <math_constants.h>
#include <cstdint>

// ---------------------------------------------------------------------------
// MHA_962072674722 (b=2, s=2048, dim=1024, 16 heads x 64)
// R14: R10 cp.async GEMMs (mma.sync bf16x3) + cp.async double-buffered
//      attention (R10 numerics: 3xBF16 S, smem-P single-tf32 PV).
//      tcgen05 is unavailable (harness PTX target lacks sm_103a features).
// ---------------------------------------------------------------------------

// ---- pre-split operand buffers -------------------------------------------
__device__ __nv_bfloat16 g_qh[4096 * 1024],  g_ql[4096 * 1024];
__device__ __nv_bfloat16 g_WqhT[1024 * 1024], g_WqlT[1024 * 1024];
__device__ __nv_bfloat16 g_WkhT[1024 * 1024], g_WklT[1024 * 1024];
__device__ __nv_bfloat16 g_WvhT[1024 * 1024], g_WvlT[1024 * 1024];
__device__ __nv_bfloat16 g_WohT[1024 * 1024], g_WolT[1024 * 1024];
__device__ __nv_bfloat16 g_Qh[4096 * 1024],  g_Ql[4096 * 1024];    // scaled Q split
__device__ __nv_bfloat16 g_Kh[4096 * 1024],  g_Kl[4096 * 1024];    // K split
__device__ float         g_VT[4096 * 1024];                        // V tf32 [b,h,d,j]
__device__ __nv_bfloat16 g_ATTh[4096 * 1024], g_ATTl[4096 * 1024];

// ---- helpers --------------------------------------------------------------
__device__ __forceinline__ unsigned f2tf(float x) {
    unsigned u; asm("cvt.rna.tf32.f32 %0, %1;" : "=r"(u) : "f"(x)); return u;
}
__device__ __forceinline__ void split_bf(float x, __nv_bfloat16& h, __nv_bfloat16& l) {
    h = __float2bfloat16(x);
    l = __float2bfloat16(x - __bfloat162float(h));
}
__device__ __forceinline__ unsigned pack2(__nv_bfloat16 a, __nv_bfloat16 b) {
    __nv_bfloat162 p = {a, b};
    return *reinterpret_cast<unsigned*>(&p);
}
__device__ __forceinline__ void mma_bf16(float c[4], const unsigned a[4],
                                         unsigned b0, unsigned b1) {
    asm("mma.sync.aligned.m16n8k16.row.col.f32.bf16.bf16.f32 "
        "{%0,%1,%2,%3},{%4,%5,%6,%7},{%8,%9},{%0,%1,%2,%3};"
        : "+f"(c[0]), "+f"(c[1]), "+f"(c[2]), "+f"(c[3])
        : "r"(a[0]), "r"(a[1]), "r"(a[2]), "r"(a[3]), "r"(b0), "r"(b1));
}
__device__ __forceinline__ void mma_tf32(float c[4], const unsigned a[4],
                                         unsigned b0, unsigned b1) {
    asm("mma.sync.aligned.m16n8k8.row.col.f32.tf32.tf32.f32 "
        "{%0,%1,%2,%3},{%4,%5,%6,%7},{%8,%9},{%0,%1,%2,%3};"
        : "+f"(c[0]), "+f"(c[1]), "+f"(c[2]), "+f"(c[3])
        : "r"(a[0]), "r"(a[1]), "r"(a[2]), "r"(a[3]), "r"(b0), "r"(b1));
}
__device__ __forceinline__ void cp16(void* dst, const void* src) {
    unsigned d = (unsigned)__cvta_generic_to_shared(dst);
    asm volatile("cp.async.cg.shared.global [%0], [%1], 16;"
                 :: "r"(d), "l"(src) : "memory");
}

// ---------------------------------------------------------------------------
// Prep: elementwise fp32 -> (hi, lo) bf16 split. n4 = elems/4.
// ---------------------------------------------------------------------------
__global__ __launch_bounds__(256) void split_mat(
    const float* __restrict__ in, __nv_bfloat16* __restrict__ h,
    __nv_bfloat16* __restrict__ l, int n4)
{
    int i = blockIdx.x * blockDim.x + threadIdx.x;
    if (i >= n4) return;
    float4 v = reinterpret_cast<const float4*>(in)[i];
    __nv_bfloat16 h0, l0, h1, l1, h2, l2, h3, l3;
    split_bf(v.x, h0, l0); split_bf(v.y, h1, l1);
    split_bf(v.z, h2, l2); split_bf(v.w, h3, l3);
    reinterpret_cast<uint2*>(h)[i] = make_uint2(pack2(h0, h1), pack2(h2, h3));
    reinterpret_cast<uint2*>(l)[i] = make_uint2(pack2(l0, l1), pack2(l2, l3));
}

// ---------------------------------------------------------------------------
// Prep: split + transpose weight block -> [n][k] bf16 hi/lo.
// ---------------------------------------------------------------------------
__global__ __launch_bounds__(256) void split_transpose(
    const float* __restrict__ W, int ldw, int col0,
    __nv_bfloat16* __restrict__ hT, __nv_bfloat16* __restrict__ lT)
{
    __shared__ float t[32][33];
    const int tx = threadIdx.x, ty = threadIdx.y;
    const int co = blockIdx.x * 32, k0 = blockIdx.y * 32;
#pragma unroll
    for (int i = ty; i < 32; i += 8)
        t[i][tx] = W[(size_t)(k0 + i) * ldw + col0 + co + tx];
    __syncthreads();
#pragma unroll
    for (int i = ty; i < 32; i += 8) {
        float v = t[tx][i];
        __nv_bfloat16 h, l;
        split_bf(v, h, l);
        hT[(size_t)(co + i) * 1024 + k0 + tx] = h;
        lT[(size_t)(co + i) * 1024 + k0 + tx] = l;
    }
}

// ---------------------------------------------------------------------------
// Pipelined 3xBF16 GEMM on pre-split operands (R10, unchanged).
// MODE 0: fp32 out. MODE 1: split bf16 out ((acc+bias)*scale).
// MODE 2: tf32 fp32 out, transposed to [b,h,d,j] (attention V).
// ---------------------------------------------------------------------------
#define ARR   (128 * 40)
#define STAGE (4 * ARR)

template <int MODE>
__global__ __launch_bounds__(256, 2) void gemm_ps(
    const __nv_bfloat16* __restrict__ Ah, const __nv_bfloat16* __restrict__ Al,
    const __nv_bfloat16* __restrict__ BhT, const __nv_bfloat16* __restrict__ BlT,
    const float* __restrict__ bias, float scale,
    float* __restrict__ outF,
    __nv_bfloat16* __restrict__ outH, __nv_bfloat16* __restrict__ outL)
{
    extern __shared__ __nv_bfloat16 sm[];
    const int tid = threadIdx.x, lane = tid & 31, w = tid >> 5;
    const int m0 = blockIdx.y * 128, n0 = blockIdx.x * 128;
    const int wm = (w & 3) * 32, wn = (w >> 2) * 64;
    const int r = lane >> 2, cq = lane & 3;

    float acc[2][8][4];
#pragma unroll
    for (int mt = 0; mt < 2; mt++)
#pragma unroll
        for (int nt = 0; nt < 8; nt++)
#pragma unroll
            for (int i = 0; i < 4; i++) acc[mt][nt][i] = 0.f;

    const int srow = tid >> 1, scb = (tid & 1) * 16;
    const __nv_bfloat16* gAh = Ah + (size_t)(m0 + srow) * 1024 + scb;
    const __nv_bfloat16* gAl = Al + (size_t)(m0 + srow) * 1024 + scb;
    const __nv_bfloat16* gBh = BhT + (size_t)(n0 + srow) * 1024 + scb;
    const __nv_bfloat16* gBl = BlT + (size_t)(n0 + srow) * 1024 + scb;
    const int so = srow * 40 + scb;

    auto stage = [&](int kt, int buf) {
        __nv_bfloat16* s = sm + buf * STAGE;
        const int go = kt * 32;
        cp16(s + so,           gAh + go); cp16(s + so + 8,           gAh + go + 8);
        cp16(s + ARR + so,     gAl + go); cp16(s + ARR + so + 8,     gAl + go + 8);
        cp16(s + 2 * ARR + so, gBh + go); cp16(s + 2 * ARR + so + 8, gBh + go + 8);
        cp16(s + 3 * ARR + so, gBl + go); cp16(s + 3 * ARR + so + 8, gBl + go + 8);
        asm volatile("cp.async.commit_group;" ::: "memory");
    };

    stage(0, 0);
    stage(1, 1);

    for (int kt = 0; kt < 32; kt++) {
        if (kt + 1 < 32) asm volatile("cp.async.wait_group 1;" ::: "memory");
        else             asm volatile("cp.async.wait_group 0;" ::: "memory");
        __syncthreads();

        const __nv_bfloat16* s = sm + (kt & 1) * STAGE;
#pragma unroll
        for (int ks = 0; ks < 2; ks++) {
            const int kk = ks * 16;
            unsigned ah[2][4], al4[2][4];
#pragma unroll
            for (int mt = 0; mt < 2; mt++) {
                const int mr = wm + mt * 16;
                ah[mt][0]  = *(const unsigned*)&s[(mr + r) * 40 + kk + cq * 2];
                ah[mt][1]  = *(const unsigned*)&s[(mr + r + 8) * 40 + kk + cq * 2];
                ah[mt][2]  = *(const unsigned*)&s[(mr + r) * 40 + kk + cq * 2 + 8];
                ah[mt][3]  = *(const unsigned*)&s[(mr + r + 8) * 40 + kk + cq * 2 + 8];
                al4[mt][0] = *(const unsigned*)&s[ARR + (mr + r) * 40 + kk + cq * 2];
                al4[mt][1] = *(const unsigned*)&s[ARR + (mr + r + 8) * 40 + kk + cq * 2];
                al4[mt][2] = *(const unsigned*)&s[ARR + (mr + r) * 40 + kk + cq * 2 + 8];
                al4[mt][3] = *(const unsigned*)&s[ARR + (mr + r + 8) * 40 + kk + cq * 2 + 8];
            }
#pragma unroll
            for (int nt = 0; nt < 8; nt++) {
                const int base = (wn + nt * 8 + r) * 40 + kk + cq * 2;
                const unsigned bh0 = *(const unsigned*)&s[2 * ARR + base];
                const unsigned bh1 = *(const unsigned*)&s[2 * ARR + base + 8];
                const unsigned bl0 = *(const unsigned*)&s[3 * ARR + base];
                const unsigned bl1 = *(const unsigned*)&s[3 * ARR + base + 8];
#pragma unroll
                for (int mt = 0; mt < 2; mt++) {
                    mma_bf16(acc[mt][nt], ah[mt],  bh0, bh1);
                    mma_bf16(acc[mt][nt], ah[mt],  bl0, bl1);
                    mma_bf16(acc[mt][nt], al4[mt], bh0, bh1);
                }
            }
        }
        __syncthreads();
        if (kt + 2 < 32) stage(kt + 2, kt & 1);
    }

    // ---- epilogue -------------------------------------------------------
#pragma unroll
    for (int nt = 0; nt < 8; nt++) {
        const int col = n0 + wn + nt * 8 + cq * 2;
        const float b0 = __ldg(bias + col), b1 = __ldg(bias + col + 1);
#pragma unroll
        for (int mt = 0; mt < 2; mt++) {
            const int row = m0 + wm + mt * 16 + r;
            float v00 = acc[mt][nt][0] + b0, v01 = acc[mt][nt][1] + b1;
            float v10 = acc[mt][nt][2] + b0, v11 = acc[mt][nt][3] + b1;
            if (MODE == 0) {
                *reinterpret_cast<float2*>(outF + (size_t)row * 1024 + col) =
                    make_float2(v00, v01);
                *reinterpret_cast<float2*>(outF + (size_t)(row + 8) * 1024 + col) =
                    make_float2(v10, v11);
            } else if (MODE == 1) {
                v00 *= scale; v01 *= scale; v10 *= scale; v11 *= scale;
                __nv_bfloat16 h0, l0, h1, l1;
                split_bf(v00, h0, l0); split_bf(v01, h1, l1);
                *(unsigned*)&outH[(size_t)row * 1024 + col] = pack2(h0, h1);
                *(unsigned*)&outL[(size_t)row * 1024 + col] = pack2(l0, l1);
                split_bf(v10, h0, l0); split_bf(v11, h1, l1);
                *(unsigned*)&outH[(size_t)(row + 8) * 1024 + col] = pack2(h0, h1);
                *(unsigned*)&outL[(size_t)(row + 8) * 1024 + col] = pack2(l0, l1);
            } else {
                // V: transposed tf32 store  VT[((b*16+h)*64+d)*2048 + j]
                const size_t base = (size_t)((row >> 11) * 16 + (col >> 6)) * 64;
                const int d = col & 63;
                outF[(base + d) * 2048 + (row & 2047)]     = __uint_as_float(f2tf(v00));
                outF[(base + d + 1) * 2048 + (row & 2047)] = __uint_as_float(f2tf(v01));
                outF[(base + d) * 2048 + ((row + 8) & 2047)]     = __uint_as_float(f2tf(v10));
                outF[(base + d + 1) * 2048 + ((row + 8) & 2047)] = __uint_as_float(f2tf(v11));
            }
        }
    }
}

// ---------------------------------------------------------------------------
// Flash attention: R10 numerics (3xBF16 S, smem-P tf32 PV) + cp.async
// double-buffered K/V staging (compiled-clean part of R12).
// smem: 2 x (Khs|Kls [64][72] bf16 + Vt [64][68] u32) + Ps [128][68] u32.
// ---------------------------------------------------------------------------
#define AK_B  (64 * 72 * 2)           // 9216 B per K array
#define AV_B  (64 * 68 * 4)           // 17408 B
#define ASTG  (2 * AK_B + AV_B)       // 35840 B per stage
#define A_SMEM (2 * ASTG + 128 * 68 * 4)   // 106496 B

__global__ __launch_bounds__(256) void attn_mma(
    const __nv_bfloat16* __restrict__ Qh, const __nv_bfloat16* __restrict__ Ql,
    const __nv_bfloat16* __restrict__ Kh, const __nv_bfloat16* __restrict__ Kl,
    const float* __restrict__ VT,
    __nv_bfloat16* __restrict__ ATTh, __nv_bfloat16* __restrict__ ATTl)
{
    extern __shared__ char smraw[];
    unsigned* Ps = reinterpret_cast<unsigned*>(smraw + 2 * ASTG);   // [128][68]

    const int tid = threadIdx.x, lane = tid & 31, w = tid >> 5;
    const int b = blockIdx.z, h = blockIdx.y, qt = blockIdx.x;
    const int r = lane >> 2, cq = lane & 3;
    const int wrow = w * 16;
    const int qrow0 = b * 2048 + qt * 128;

    // --- Q fragments from pre-split global ---
    unsigned qh[4][4], ql4[4][4];
#pragma unroll
    for (int ks = 0; ks < 4; ks++)
#pragma unroll
        for (int fi = 0; fi < 4; fi++) {
            const int rr = qrow0 + wrow + r + (fi & 1) * 8;
            const int cc = h * 64 + ks * 16 + cq * 2 + (fi >> 1) * 8;
            qh[ks][fi]  = *(const unsigned*)&Qh[(size_t)rr * 1024 + cc];
            ql4[ks][fi] = *(const unsigned*)&Ql[(size_t)rr * 1024 + cc];
        }

    float o[8][4];
#pragma unroll
    for (int nt = 0; nt < 8; nt++)
#pragma unroll
        for (int i = 0; i < 4; i++) o[nt][i] = 0.f;
    float mr0 = -CUDART_INF_F, mr1 = -CUDART_INF_F;
    float lr0 = 0.f, lr1 = 0.f;

    // staging maps
    const int srow = tid >> 2, kcb = (tid & 3) * 16;   // K: row, 16-elem chunk
    const size_t kgbase = (size_t)(b * 2048 + srow) * 1024 + h * 64 + kcb;
    const size_t vgbase = (size_t)((b * 16 + h) * 64 + srow) * 2048 + kcb;

    auto stage = [&](int kt, int buf) {
        char* s = smraw + buf * ASTG;
        const size_t kg = kgbase + (size_t)kt * 64 * 1024;
        const size_t vg = vgbase + kt * 64;
        __nv_bfloat16* khs = reinterpret_cast<__nv_bfloat16*>(s);
        __nv_bfloat16* kls = reinterpret_cast<__nv_bfloat16*>(s + AK_B);
        float* vts = reinterpret_cast<float*>(s + 2 * AK_B);
        cp16(&khs[srow * 72 + kcb],     Kh + kg);
        cp16(&khs[srow * 72 + kcb + 8], Kh + kg + 8);
        cp16(&kls[srow * 72 + kcb],     Kl + kg);
        cp16(&kls[srow * 72 + kcb + 8], Kl + kg + 8);
#pragma unroll
        for (int i = 0; i < 4; i++)
            cp16(&vts[srow * 68 + kcb + i * 4], VT + vg + i * 4);
        asm volatile("cp.async.commit_group;" ::: "memory");
    };

    stage(0, 0);

    for (int kt = 0; kt < 32; kt++) {
        if (kt + 1 < 32) {
            stage(kt + 1, (kt + 1) & 1);
            asm volatile("cp.async.wait_group 1;" ::: "memory");
        } else {
            asm volatile("cp.async.wait_group 0;" ::: "memory");
        }
        __syncthreads();

        const char* s = smraw + (kt & 1) * ASTG;
        const __nv_bfloat16* Khs = reinterpret_cast<const __nv_bfloat16*>(s);
        const __nv_bfloat16* Kls = reinterpret_cast<const __nv_bfloat16*>(s + AK_B);
        const unsigned* Vs = reinterpret_cast<const unsigned*>(s + 2 * AK_B);

        // ---- S = Q @ K^T (3xBF16) ----
        float sc[8][4];
#pragma unroll
        for (int nt = 0; nt < 8; nt++)
#pragma unroll
            for (int i = 0; i < 4; i++) sc[nt][i] = 0.f;
#pragma unroll
        for (int ks = 0; ks < 4; ks++) {
            const int kk = ks * 16;
#pragma unroll
            for (int nt = 0; nt < 8; nt++) {
                const int base = (nt * 8 + r) * 72 + kk + cq * 2;
                const unsigned bh0 = *(const unsigned*)&Khs[base];
                const unsigned bh1 = *(const unsigned*)&Khs[base + 8];
                const unsigned bl0 = *(const unsigned*)&Kls[base];
                const unsigned bl1 = *(const unsigned*)&Kls[base + 8];
                mma_bf16(sc[nt], qh[ks],  bh0, bh1);
                mma_bf16(sc[nt], qh[ks],  bl0, bl1);
                mma_bf16(sc[nt], ql4[ks], bh0, bh1);
            }
        }

        // ---- online softmax ----
        float tm0 = -CUDART_INF_F, tm1 = -CUDART_INF_F;
#pragma unroll
        for (int nt = 0; nt < 8; nt++) {
            tm0 = fmaxf(tm0, fmaxf(sc[nt][0], sc[nt][1]));
            tm1 = fmaxf(tm1, fmaxf(sc[nt][2], sc[nt][3]));
        }
        tm0 = fmaxf(tm0, __shfl_xor_sync(0xffffffffu, tm0, 1));
        tm0 = fmaxf(tm0, __shfl_xor_sync(0xffffffffu, tm0, 2));
        tm1 = fmaxf(tm1, __shfl_xor_sync(0xffffffffu, tm1, 1));
        tm1 = fmaxf(tm1, __shfl_xor_sync(0xffffffffu, tm1, 2));

        const float mn0 = fmaxf(mr0, tm0), mn1 = fmaxf(mr1, tm1);
        const float c0 = __expf(mr0 - mn0), c1 = __expf(mr1 - mn1);
        float ps0 = 0.f, ps1 = 0.f;
#pragma unroll
        for (int nt = 0; nt < 8; nt++) {
            const float p00 = __expf(sc[nt][0] - mn0);
            const float p01 = __expf(sc[nt][1] - mn0);
            const float p10 = __expf(sc[nt][2] - mn1);
            const float p11 = __expf(sc[nt][3] - mn1);
            ps0 += p00 + p01; ps1 += p10 + p11;
            const int col = nt * 8 + cq * 2;
            *reinterpret_cast<uint2*>(&Ps[(wrow + r) * 68 + col]) =
                make_uint2(f2tf(p00), f2tf(p01));
            *reinterpret_cast<uint2*>(&Ps[(wrow + r + 8) * 68 + col]) =
                make_uint2(f2tf(p10), f2tf(p11));
            o[nt][0] *= c0; o[nt][1] *= c0; o[nt][2] *= c1; o[nt][3] *= c1;
        }
        ps0 += __shfl_xor_sync(0xffffffffu, ps0, 1);
        ps0 += __shfl_xor_sync(0xffffffffu, ps0, 2);
        ps1 += __shfl_xor_sync(0xffffffffu, ps1, 1);
        ps1 += __shfl_xor_sync(0xffffffffu, ps1, 2);
        lr0 = lr0 * c0 + ps0; lr1 = lr1 * c1 + ps1;
        mr0 = mn0; mr1 = mn1;
        __syncwarp();   // Ps rows wrow..wrow+15 are warp-private

        // ---- O += P @ V (single tf32) ----
#pragma unroll
        for (int ks = 0; ks < 8; ks++) {
            const int kk = ks * 8;
            unsigned a[4];
            a[0] = Ps[(wrow + r) * 68 + kk + cq];
            a[1] = Ps[(wrow + r + 8) * 68 + kk + cq];
            a[2] = Ps[(wrow + r) * 68 + kk + cq + 4];
            a[3] = Ps[(wrow + r + 8) * 68 + kk + cq + 4];
#pragma unroll
            for (int nt = 0; nt < 8; nt++) {
                const int nn = (nt * 8 + r) * 68;
                mma_tf32(o[nt], a, Vs[nn + kk + cq], Vs[nn + kk + cq + 4]);
            }
        }
        __syncthreads();   // readers done before buffer reuse
    }

    // ---- epilogue: split store ----
    const float i0 = 1.f / lr0, i1 = 1.f / lr1;
#pragma unroll
    for (int nt = 0; nt < 8; nt++) {
        const int col = h * 64 + nt * 8 + cq * 2;
        const int row = qrow0 + wrow + r;
        __nv_bfloat16 h0, l0, h1, l1;
        split_bf(o[nt][0] * i0, h0, l0); split_bf(o[nt][1] * i0, h1, l1);
        *(unsigned*)&ATTh[(size_t)row * 1024 + col] = pack2(h0, h1);
        *(unsigned*)&ATTl[(size_t)row * 1024 + col] = pack2(l0, l1);
        split_bf(o[nt][2] * i1, h0, l0); split_bf(o[nt][3] * i1, h1, l1);
        *(unsigned*)&ATTh[(size_t)(row + 8) * 1024 + col] = pack2(h0, h1);
        *(unsigned*)&ATTl[(size_t)(row + 8) * 1024 + col] = pack2(l0, l1);
    }
}

// ---------------------------------------------------------------------------
extern "C" void kernel_launch(void* const* d_in, const int* in_sizes, int n_in,
                              void* d_out, int out_size)
{
    const float* q   = (const float*)d_in[0];
    const float* Wq  = (const float*)d_in[1];
    const float* bq  = (const float*)d_in[2];
    const float* Wkv = (const float*)d_in[3];
    const float* bkv = (const float*)d_in[4];
    const float* Wo  = (const float*)d_in[5];
    const float* bo  = (const float*)d_in[6];
    float* out = (float*)d_out;

    __nv_bfloat16 *qh, *ql, *WqhT, *WqlT, *WkhT, *WklT, *WvhT, *WvlT, *WohT, *WolT;
    __nv_bfloat16 *Qh, *Ql, *Kh, *Kl, *ATTh, *ATTl;
    float *VT;
    cudaGetSymbolAddress((void**)&qh, g_qh);     cudaGetSymbolAddress((void**)&ql, g_ql);
    cudaGetSymbolAddress((void**)&WqhT, g_WqhT); cudaGetSymbolAddress((void**)&WqlT, g_WqlT);
    cudaGetSymbolAddress((void**)&WkhT, g_WkhT); cudaGetSymbolAddress((void**)&WklT, g_WklT);
    cudaGetSymbolAddress((void**)&WvhT, g_WvhT); cudaGetSymbolAddress((void**)&WvlT, g_WvlT);
    cudaGetSymbolAddress((void**)&WohT, g_WohT); cudaGetSymbolAddress((void**)&WolT, g_WolT);
    cudaGetSymbolAddress((void**)&Qh, g_Qh);     cudaGetSymbolAddress((void**)&Ql, g_Ql);
    cudaGetSymbolAddress((void**)&Kh, g_Kh);     cudaGetSymbolAddress((void**)&Kl, g_Kl);
    cudaGetSymbolAddress((void**)&VT, g_VT);
    cudaGetSymbolAddress((void**)&ATTh, g_ATTh); cudaGetSymbolAddress((void**)&ATTl, g_ATTl);

    const int GEMM_SMEM = 2 * STAGE * 2;        // 81920 B
    cudaFuncSetAttribute(gemm_ps<0>, cudaFuncAttributeMaxDynamicSharedMemorySize, GEMM_SMEM);
    cudaFuncSetAttribute(gemm_ps<1>, cudaFuncAttributeMaxDynamicSharedMemorySize, GEMM_SMEM);
    cudaFuncSetAttribute(gemm_ps<2>, cudaFuncAttributeMaxDynamicSharedMemorySize, GEMM_SMEM);
    cudaFuncSetAttribute(attn_mma, cudaFuncAttributeMaxDynamicSharedMemorySize, A_SMEM);

    // --- prep ---
    split_mat<<<4096, 256>>>(q, qh, ql, 4096 * 1024 / 4);
    split_transpose<<<dim3(32, 32), dim3(32, 8)>>>(Wq, 1024, 0, WqhT, WqlT);
    split_transpose<<<dim3(32, 32), dim3(32, 8)>>>(Wkv, 2048, 0, WkhT, WklT);
    split_transpose<<<dim3(32, 32), dim3(32, 8)>>>(Wkv, 2048, 1024, WvhT, WvlT);
    split_transpose<<<dim3(32, 32), dim3(32, 8)>>>(Wo, 1024, 0, WohT, WolT);

    // --- projections ---
    gemm_ps<1><<<dim3(8, 32), 256, GEMM_SMEM>>>(qh, ql, WqhT, WqlT, bq, 0.125f,
                                                nullptr, Qh, Ql);
    gemm_ps<1><<<dim3(8, 32), 256, GEMM_SMEM>>>(qh, ql, WkhT, WklT, bkv, 1.0f,
                                                nullptr, Kh, Kl);
    gemm_ps<2><<<dim3(8, 32), 256, GEMM_SMEM>>>(qh, ql, WvhT, WvlT, bkv + 1024, 1.0f,
                                                VT, nullptr, nullptr);
    // --- attention ---
    attn_mma<<<dim3(16, 16, 2), 256, A_SMEM>>>(Qh, Ql, Kh, Kl, VT, ATTh, ATTl);
    // --- output projection ---
    gemm_ps<0><<<dim3(8, 32), 256, GEMM_SMEM>>>(ATTh, ATTl, WohT, WolT, bo, 1.0f,
                                                out, nullptr, nullptr);
}